// round 10
// baseline (speedup 1.0000x reference)
#include <cuda_runtime.h>
#include <cuda_fp16.h>
#include <math.h>

#define NN 50000
#define NE 800000
#define ETOT (NE + NN)          // edges + self loops
#define HEADS 8
#define HID 32
#define D1 (HEADS * HID)        // 256
#define D2 16
#define NEG_SLOPE 0.2f
#define FULL 0xffffffffu
#define CAP 64                  // max bucket slots (deg ~ Poisson(17); P(>64)~1e-19)

// padded smem index: k + k/32 -> stride-8 access becomes conflict-free
#define PAD(k) ((k) + ((k) >> 5))
// W2 swizzle: rotate channel by k>>3 so lanes hit distinct banks in the GEMV
#define W2IDX(k, c) (((k) << 4) | (((c) + ((k) >> 3)) & 15))

// ---------------- scratch (device globals; zero-initialized at load) ---------
__device__ int g_cursor[NN];                  // invariant: zero at launch entry
__device__ unsigned short g_bkt[NN * CAP];    // per-dst src lists (6.4 MB)

__device__ __align__(16) float4 g_x4[NN];           // packed node features
__device__ __align__(16) __half g_h2h[NN * D2];     // layer2 features, fp16
__device__ float g_as2[NN];
__device__ float g_ad2[NN];
__device__ float g_As1[24];   // [i*8+h]: att_src folded through W1 (3x8)
__device__ float g_Ad1[24];

__device__ __forceinline__ float lrelu(float x) {
    return x > 0.f ? x : NEG_SLOPE * x;
}

// ---------------- bucket build + x packing + folded attention prep -----------
__global__ void k_scatter(const int* __restrict__ ei,
                          const float* __restrict__ x,
                          const float* __restrict__ W1,
                          const float* __restrict__ atts1,
                          const float* __restrict__ attd1) {
    if (blockIdx.x == gridDim.x - 1) {
        int t = threadIdx.x;
        if (t < 24) {
            int i = t >> 3, h = t & 7;
            float ss = 0.f, sd = 0.f;
            #pragma unroll
            for (int c = 0; c < HID; c++) {
                float w = __ldg(&W1[i * D1 + h * HID + c]);
                ss = fmaf(w, __ldg(&atts1[h * HID + c]), ss);
                sd = fmaf(w, __ldg(&attd1[h * HID + c]), sd);
            }
            g_As1[i * 8 + h] = ss;
            g_Ad1[i * 8 + h] = sd;
        }
        return;
    }
    int e = blockIdx.x * 256 + threadIdx.x;
    if (e >= ETOT) return;
    if (e < NN) {
        g_x4[e] = make_float4(__ldg(&x[e * 3 + 0]), __ldg(&x[e * 3 + 1]),
                              __ldg(&x[e * 3 + 2]), 0.f);
    }
    int src, dst;
    if (e < NE) { src = ei[e]; dst = ei[NE + e]; }
    else        { src = e - NE; dst = e - NE; }
    int slot = atomicAdd(&g_cursor[dst], 1);
    if (slot < CAP) g_bkt[dst * CAP + slot] = (unsigned short)src;
}

// ---------------- fused layer1 agg + ELU + layer2 node transform -------------
// 512 threads = 16 warps = 16 nodes/block; grid 3125 (= 50000/16 exactly).
// Per warp: gather-softmax-agg over x[src] (rank-3 trick) -> 256 ELU'd channels
// in registers (8/lane) -> 256x16 GEMV via smem W2 + butterfly all-reduce ->
// h2, as2, ad2 written by lane 0. No hmid global round-trip.
__global__ __launch_bounds__(512)
void k_l1_fused(const float* __restrict__ W1,
                const float* __restrict__ bias1,
                const float* __restrict__ W2,
                const float* __restrict__ atts2,
                const float* __restrict__ attd2) {
    __shared__ float W1s[PAD(767) + 1];
    __shared__ float b1s[PAD(255) + 1];
    __shared__ float W2s[D1 * D2];       // 16 KB, swizzle-stored
    __shared__ float aS2[16], aD2[16];
    for (int i = threadIdx.x; i < 768; i += 512) W1s[PAD(i)] = W1[i];
    if (threadIdx.x < 256) b1s[PAD(threadIdx.x)] = bias1[threadIdx.x];
    for (int i = threadIdx.x; i < D1 * D2; i += 512) {
        int k = i >> 4, c = i & 15;
        W2s[W2IDX(k, c)] = W2[i];
    }
    if (threadIdx.x < 16) {
        aS2[threadIdx.x] = atts2[threadIdx.x];
        aD2[threadIdx.x] = attd2[threadIdx.x];
    }
    __syncthreads();

    int n = blockIdx.x * 16 + (threadIdx.x >> 5);   // always < NN (3125*16=50000)
    int lane = threadIdx.x & 31;
    int deg  = min(g_cursor[n], CAP);
    const unsigned short* row = g_bkt + n * CAP;

    int q = lane & 3;     // heads q and q+4
    int g = lane >> 2;    // edge subgroup 0..7

    float A00 = g_As1[q],     A01 = g_As1[8 + q],  A02 = g_As1[16 + q];
    float A10 = g_As1[4 + q], A11 = g_As1[12 + q], A12 = g_As1[20 + q];
    float4 xn = g_x4[n];
    float adh0 = fmaf(xn.x, g_Ad1[q],     fmaf(xn.y, g_Ad1[8 + q],  xn.z * g_Ad1[16 + q]));
    float adh1 = fmaf(xn.x, g_Ad1[4 + q], fmaf(xn.y, g_Ad1[12 + q], xn.z * g_Ad1[20 + q]));

    float sx0 = 0.f, sy0 = 0.f, sz0 = 0.f, sw0 = 0.f;
    float sx1 = 0.f, sy1 = 0.f, sz1 = 0.f, sw1 = 0.f;

    for (int j = g; j < deg; j += 8) {
        int s = (int)row[j];                 // 4 lanes same addr -> broadcast
        float4 xs = __ldg(&g_x4[s]);         // one LDG.128 per subgroup
        float as0 = fmaf(xs.x, A00, fmaf(xs.y, A01, xs.z * A02));
        float as1 = fmaf(xs.x, A10, fmaf(xs.y, A11, xs.z * A12));
        float w0 = __expf(lrelu(as0 + adh0));
        float w1 = __expf(lrelu(as1 + adh1));
        sw0 += w0;
        sx0 = fmaf(w0, xs.x, sx0); sy0 = fmaf(w0, xs.y, sy0); sz0 = fmaf(w0, xs.z, sz0);
        sw1 += w1;
        sx1 = fmaf(w1, xs.x, sx1); sy1 = fmaf(w1, xs.y, sy1); sz1 = fmaf(w1, xs.z, sz1);
    }
    #pragma unroll
    for (int off = 4; off <= 16; off <<= 1) {
        sx0 += __shfl_xor_sync(FULL, sx0, off);
        sy0 += __shfl_xor_sync(FULL, sy0, off);
        sz0 += __shfl_xor_sync(FULL, sz0, off);
        sw0 += __shfl_xor_sync(FULL, sw0, off);
        sx1 += __shfl_xor_sync(FULL, sx1, off);
        sy1 += __shfl_xor_sync(FULL, sy1, off);
        sz1 += __shfl_xor_sync(FULL, sz1, off);
        sw1 += __shfl_xor_sync(FULL, sw1, off);
    }

    // layer1 epilogue: lane covers channels [lane*8, lane*8+8), head hc = lane>>2
    int hc = lane >> 2;
    int srcl = hc & 3;
    float tx0 = __shfl_sync(FULL, sx0, srcl), tx1 = __shfl_sync(FULL, sx1, srcl);
    float ty0 = __shfl_sync(FULL, sy0, srcl), ty1 = __shfl_sync(FULL, sy1, srcl);
    float tz0 = __shfl_sync(FULL, sz0, srcl), tz1 = __shfl_sync(FULL, sz1, srcl);
    float tw0 = __shfl_sync(FULL, sw0, srcl), tw1 = __shfl_sync(FULL, sw1, srcl);
    bool lo = hc < 4;
    float ex = lo ? tx0 : tx1;
    float ey = lo ? ty0 : ty1;
    float ez = lo ? tz0 : tz1;
    float ew = lo ? tw0 : tw1;
    float inv = 1.0f / (ew + 1e-16f);
    ex *= inv; ey *= inv; ez *= inv;

    int c0 = lane * 8;
    float o[8];
    #pragma unroll
    for (int i = 0; i < 8; i++) {
        int k = c0 + i;
        float v = fmaf(ex, W1s[PAD(k)],
                  fmaf(ey, W1s[PAD(256 + k)], ez * W1s[PAD(512 + k)]));
        v += b1s[PAD(k)];
        o[i] = v > 0.f ? v : (__expf(v) - 1.0f);     // ELU, fp32 (no fp16 trip)
    }

    // layer2 node transform: p[c] = sum_k hmid[k] * W2[k][c]
    // lane's slice: k in [c0, c0+8); swizzled W2s -> lanes hit distinct banks
    float p[16];
    #pragma unroll
    for (int c = 0; c < 16; c++) {
        float acc = 0.f;
        #pragma unroll
        for (int i = 0; i < 8; i++) {
            int k = c0 + i;   // k>>3 == lane for i<8
            acc = fmaf(o[i], W2s[(k << 4) | (((c + lane) & 15))], acc);
        }
        p[c] = acc;
    }
    // butterfly all-reduce of 16 values across the warp
    #pragma unroll
    for (int off = 1; off < 32; off <<= 1) {
        #pragma unroll
        for (int c = 0; c < 16; c++)
            p[c] += __shfl_xor_sync(FULL, p[c], off);
    }
    if (lane == 0) {
        float sa = 0.f, sd = 0.f;
        #pragma unroll
        for (int c = 0; c < 16; c++) {
            sa = fmaf(p[c], aS2[c], sa);
            sd = fmaf(p[c], aD2[c], sd);
        }
        g_as2[n] = sa;
        g_ad2[n] = sd;
        __half2 hh[8];
        #pragma unroll
        for (int t = 0; t < 8; t++) hh[t] = __floats2half2_rn(p[2 * t], p[2 * t + 1]);
        uint4 u0, u1;
        u0.x = *reinterpret_cast<unsigned int*>(&hh[0]);
        u0.y = *reinterpret_cast<unsigned int*>(&hh[1]);
        u0.z = *reinterpret_cast<unsigned int*>(&hh[2]);
        u0.w = *reinterpret_cast<unsigned int*>(&hh[3]);
        u1.x = *reinterpret_cast<unsigned int*>(&hh[4]);
        u1.y = *reinterpret_cast<unsigned int*>(&hh[5]);
        u1.z = *reinterpret_cast<unsigned int*>(&hh[6]);
        u1.w = *reinterpret_cast<unsigned int*>(&hh[7]);
        uint4* dst = reinterpret_cast<uint4*>(g_h2h + n * D2);
        dst[0] = u0;
        dst[1] = u1;
    }
}

// ---------------- layer 2: single-pass softmax-agg ---------------------------
// one warp per dst node; 8 edge subgroups x 4 lanes, each lane owns 4 channels.
// Re-zeros g_cursor after the last read (restores launch invariant).
__global__ void k_l2_agg(const float* __restrict__ bias2,
                         float* __restrict__ out) {
    int n = blockIdx.x * 8 + (threadIdx.x >> 5);
    if (n >= NN) return;
    int lane = threadIdx.x & 31;
    int deg  = min(g_cursor[n], CAP);
    const unsigned short* row = g_bkt + n * CAP;
    float adn = g_ad2[n];

    int q = lane & 3;         // channel quad owner: channels 4q..4q+3
    int g = lane >> 2;        // edge subgroup 0..7

    float a0 = 0.f, a1 = 0.f, a2 = 0.f, a3 = 0.f, wsum = 0.f;
    for (int j = g; j < deg; j += 8) {
        int s = (int)row[j];                           // broadcast in subgroup
        float w = __expf(lrelu(g_as2[s] + adn));       // broadcast load
        uint2 v = *reinterpret_cast<const uint2*>(g_h2h + s * D2 + q * 4);
        float2 f0 = __half22float2(*reinterpret_cast<__half2*>(&v.x));
        float2 f1 = __half22float2(*reinterpret_cast<__half2*>(&v.y));
        a0 = fmaf(w, f0.x, a0);
        a1 = fmaf(w, f0.y, a1);
        a2 = fmaf(w, f1.x, a2);
        a3 = fmaf(w, f1.y, a3);
        wsum += w;
    }
    #pragma unroll
    for (int off = 4; off <= 16; off <<= 1) {
        a0   += __shfl_xor_sync(FULL, a0, off);
        a1   += __shfl_xor_sync(FULL, a1, off);
        a2   += __shfl_xor_sync(FULL, a2, off);
        a3   += __shfl_xor_sync(FULL, a3, off);
        wsum += __shfl_xor_sync(FULL, wsum, off);
    }
    if (lane < 4) {
        float inv = 1.0f / (wsum + 1e-16f);
        int c = q * 4;
        float4 r;
        r.x = a0 * inv + bias2[c];
        r.y = a1 * inv + bias2[c + 1];
        r.z = a2 * inv + bias2[c + 2];
        r.w = a3 * inv + bias2[c + 3];
        *reinterpret_cast<float4*>(out + n * D2 + c) = r;
    }
    if (lane == 0) g_cursor[n] = 0;   // restore zero invariant
}

// ---------------- launch ------------------------------------------------------
extern "C" void kernel_launch(void* const* d_in, const int* in_sizes, int n_in,
                              void* d_out, int out_size) {
    const float* x      = (const float*)d_in[0];
    const int*   ei     = (const int*)d_in[1];   // JAX x64 disabled -> int32
    const float* W1     = (const float*)d_in[2];
    const float* atts1  = (const float*)d_in[3];
    const float* attd1  = (const float*)d_in[4];
    const float* bias1  = (const float*)d_in[5];
    const float* W2     = (const float*)d_in[6];
    const float* atts2  = (const float*)d_in[7];
    const float* attd2  = (const float*)d_in[8];
    const float* bias2  = (const float*)d_in[9];
    float* out = (float*)d_out;

    int eb = (ETOT + 255) / 256;
    k_scatter<<<eb + 1, 256>>>(ei, x, W1, atts1, attd1);   // +1 block does prep
    k_l1_fused<<<NN / 16, 512>>>(W1, bias1, W2, atts2, attd2);
    k_l2_agg<<<(NN + 7) / 8, 256>>>(bias2, out);
}

// round 11
// speedup vs baseline: 1.0777x; 1.0777x over previous
#include <cuda_runtime.h>
#include <cuda_fp16.h>
#include <math.h>

#define NN 50000
#define NE 800000
#define ETOT (NE + NN)          // edges + self loops
#define HEADS 8
#define HID 32
#define D1 (HEADS * HID)        // 256
#define D2 16
#define NEG_SLOPE 0.2f
#define FULL 0xffffffffu
#define CAP 64                  // max bucket slots (deg ~ Poisson(17); P(>64)~1e-19)

#define NE4 (NE / 4)            // 200000
#define NN4 (NN / 4)            // 12500
#define SCAT_T (NE4 + NN4)      // 212500 worker threads

// padded smem index: k + k/32 -> stride-8 access becomes conflict-free
#define PAD(k) ((k) + ((k) >> 5))

// ---------------- scratch (device globals; zero-initialized at load) ---------
__device__ int g_cursor[NN];                  // invariant: zero at launch entry
__device__ unsigned short g_bkt[NN * CAP];    // per-dst src lists (6.4 MB)

__device__ __align__(16) float4 g_x4[NN];           // packed node features
__device__ __align__(16) __half g_hmid_h[NN * D1];  // elu(layer1 out), fp16
__device__ __align__(16) __half g_h2h[NN * D2];     // layer2 features, fp16
__device__ float g_as2[NN];
__device__ float g_ad2[NN];
__device__ float g_As1[24];   // [i*8+h]: att_src folded through W1 (3x8)
__device__ float g_Ad1[24];

__device__ __forceinline__ float lrelu(float x) {
    return x > 0.f ? x : NEG_SLOPE * x;
}

__device__ __forceinline__ void bput(int dst, int src) {
    int slot = atomicAdd(&g_cursor[dst], 1);
    if (slot < CAP) g_bkt[dst * CAP + slot] = (unsigned short)src;
}

// ---------------- bucket build (4 edges/thread) + x packing + att prep -------
__global__ void k_scatter(const int* __restrict__ ei,
                          const float* __restrict__ x,
                          const float* __restrict__ W1,
                          const float* __restrict__ atts1,
                          const float* __restrict__ attd1) {
    if (blockIdx.x == gridDim.x - 1) {
        int t = threadIdx.x;
        if (t < 24) {
            int i = t >> 3, h = t & 7;
            float ss = 0.f, sd = 0.f;
            #pragma unroll
            for (int c = 0; c < HID; c++) {
                float w = __ldg(&W1[i * D1 + h * HID + c]);
                ss = fmaf(w, __ldg(&atts1[h * HID + c]), ss);
                sd = fmaf(w, __ldg(&attd1[h * HID + c]), sd);
            }
            g_As1[i * 8 + h] = ss;
            g_Ad1[i * 8 + h] = sd;
        }
        return;
    }
    int t = blockIdx.x * 256 + threadIdx.x;
    if (t < NE4) {
        // 4 real edges via vectorized loads
        int4 S = __ldg(reinterpret_cast<const int4*>(ei) + t);
        int4 D = __ldg(reinterpret_cast<const int4*>(ei + NE) + t);
        bput(D.x, S.x);
        bput(D.y, S.y);
        bput(D.z, S.z);
        bput(D.w, S.w);
    } else if (t < SCAT_T) {
        // 4 nodes: pack x into float4 + insert self-loops
        int m = t - NE4;
        int n0 = m * 4;
        const float4* xv = reinterpret_cast<const float4*>(x) + m * 3;
        float4 a = __ldg(xv), b = __ldg(xv + 1), c = __ldg(xv + 2);
        g_x4[n0 + 0] = make_float4(a.x, a.y, a.z, 0.f);
        g_x4[n0 + 1] = make_float4(a.w, b.x, b.y, 0.f);
        g_x4[n0 + 2] = make_float4(b.z, b.w, c.x, 0.f);
        g_x4[n0 + 3] = make_float4(c.y, c.z, c.w, 0.f);
        bput(n0 + 0, n0 + 0);
        bput(n0 + 1, n0 + 1);
        bput(n0 + 2, n0 + 2);
        bput(n0 + 3, n0 + 3);
    }
}

// ---------------- layer 1: fused gather-softmax-agg-transform + ELU ----------
// 512 threads = 16 warps = 16 nodes/block; grid 3125 (exact). One warp/node;
// 8 edge subgroups x 4 lanes; each lane covers heads q and q+4.
__global__ __launch_bounds__(512)
void k_l1_agg(const float* __restrict__ W1,
              const float* __restrict__ bias1) {
    __shared__ float W1s[PAD(767) + 1];   // padded, conflict-free for stride-8
    __shared__ float b1s[PAD(255) + 1];
    for (int i = threadIdx.x; i < 768; i += 512) W1s[PAD(i)] = W1[i];
    if (threadIdx.x < 256) b1s[PAD(threadIdx.x)] = bias1[threadIdx.x];
    __syncthreads();

    int n = blockIdx.x * 16 + (threadIdx.x >> 5);   // 3125*16 = 50000 exact
    int lane = threadIdx.x & 31;
    int deg  = min(g_cursor[n], CAP);
    const unsigned short* row = g_bkt + n * CAP;

    int q = lane & 3;     // heads q and q+4
    int g = lane >> 2;    // edge subgroup 0..7

    float A00 = g_As1[q],     A01 = g_As1[8 + q],  A02 = g_As1[16 + q];
    float A10 = g_As1[4 + q], A11 = g_As1[12 + q], A12 = g_As1[20 + q];
    float4 xn = g_x4[n];
    float adh0 = fmaf(xn.x, g_Ad1[q],     fmaf(xn.y, g_Ad1[8 + q],  xn.z * g_Ad1[16 + q]));
    float adh1 = fmaf(xn.x, g_Ad1[4 + q], fmaf(xn.y, g_Ad1[12 + q], xn.z * g_Ad1[20 + q]));

    float sx0 = 0.f, sy0 = 0.f, sz0 = 0.f, sw0 = 0.f;
    float sx1 = 0.f, sy1 = 0.f, sz1 = 0.f, sw1 = 0.f;

    for (int j = g; j < deg; j += 8) {
        int s = (int)row[j];                 // 4 lanes same addr -> broadcast
        float4 xs = __ldg(&g_x4[s]);         // one LDG.128 per subgroup
        float as0 = fmaf(xs.x, A00, fmaf(xs.y, A01, xs.z * A02));
        float as1 = fmaf(xs.x, A10, fmaf(xs.y, A11, xs.z * A12));
        float w0 = __expf(lrelu(as0 + adh0));
        float w1 = __expf(lrelu(as1 + adh1));
        sw0 += w0;
        sx0 = fmaf(w0, xs.x, sx0); sy0 = fmaf(w0, xs.y, sy0); sz0 = fmaf(w0, xs.z, sz0);
        sw1 += w1;
        sx1 = fmaf(w1, xs.x, sx1); sy1 = fmaf(w1, xs.y, sy1); sz1 = fmaf(w1, xs.z, sz1);
    }
    #pragma unroll
    for (int off = 4; off <= 16; off <<= 1) {
        sx0 += __shfl_xor_sync(FULL, sx0, off);
        sy0 += __shfl_xor_sync(FULL, sy0, off);
        sz0 += __shfl_xor_sync(FULL, sz0, off);
        sw0 += __shfl_xor_sync(FULL, sw0, off);
        sx1 += __shfl_xor_sync(FULL, sx1, off);
        sy1 += __shfl_xor_sync(FULL, sy1, off);
        sz1 += __shfl_xor_sync(FULL, sz1, off);
        sw1 += __shfl_xor_sync(FULL, sw1, off);
    }

    // epilogue: lane covers channels [lane*8, lane*8+8), head hc = lane>>2
    int hc = lane >> 2;
    int srcl = hc & 3;
    float tx0 = __shfl_sync(FULL, sx0, srcl), tx1 = __shfl_sync(FULL, sx1, srcl);
    float ty0 = __shfl_sync(FULL, sy0, srcl), ty1 = __shfl_sync(FULL, sy1, srcl);
    float tz0 = __shfl_sync(FULL, sz0, srcl), tz1 = __shfl_sync(FULL, sz1, srcl);
    float tw0 = __shfl_sync(FULL, sw0, srcl), tw1 = __shfl_sync(FULL, sw1, srcl);
    bool lo = hc < 4;
    float ex = lo ? tx0 : tx1;
    float ey = lo ? ty0 : ty1;
    float ez = lo ? tz0 : tz1;
    float ew = lo ? tw0 : tw1;
    float inv = 1.0f / (ew + 1e-16f);
    ex *= inv; ey *= inv; ez *= inv;

    int c0 = lane * 8;
    float o[8];
    #pragma unroll
    for (int i = 0; i < 8; i++) {
        int k = c0 + i;
        float v = fmaf(ex, W1s[PAD(k)],
                  fmaf(ey, W1s[PAD(256 + k)], ez * W1s[PAD(512 + k)]));
        v += b1s[PAD(k)];
        o[i] = v > 0.f ? v : (__expf(v) - 1.0f);
    }
    __half2 p0 = __floats2half2_rn(o[0], o[1]);
    __half2 p1 = __floats2half2_rn(o[2], o[3]);
    __half2 p2 = __floats2half2_rn(o[4], o[5]);
    __half2 p3 = __floats2half2_rn(o[6], o[7]);
    uint4 pack;
    pack.x = *reinterpret_cast<unsigned int*>(&p0);
    pack.y = *reinterpret_cast<unsigned int*>(&p1);
    pack.z = *reinterpret_cast<unsigned int*>(&p2);
    pack.w = *reinterpret_cast<unsigned int*>(&p3);
    reinterpret_cast<uint4*>(g_hmid_h)[n * 32 + lane] = pack;
}

// ---------------- layer 2: node transform (256 -> 16), fp16 in/out -----------
// 1024 threads = 64 nodes/block -> 4x less W2 smem-fill traffic than 256.
__global__ __launch_bounds__(1024)
void k_l2_node(const float* __restrict__ W2,
               const float* __restrict__ att_s,
               const float* __restrict__ att_d) {
    __shared__ float W2s[D1 * D2];   // 16 KB
    for (int i = threadIdx.x; i < D1 * D2; i += 1024) W2s[i] = W2[i];
    __syncthreads();

    int grp = threadIdx.x >> 4;
    int c   = threadIdx.x & 15;
    int n = blockIdx.x * 64 + grp;
    if (n >= NN) return;

    const uint4* row = reinterpret_cast<const uint4*>(g_hmid_h + n * D1);
    float acc = 0.f;
    #pragma unroll 8
    for (int q = 0; q < 32; q++) {
        uint4 v = row[q];
        int k = q * 8;
        const __half2* p = reinterpret_cast<const __half2*>(&v);
        #pragma unroll
        for (int t = 0; t < 4; t++) {
            float2 f = __half22float2(p[t]);
            acc = fmaf(f.x, W2s[(k + 2 * t) * D2 + c], acc);
            acc = fmaf(f.y, W2s[(k + 2 * t + 1) * D2 + c], acc);
        }
    }
    g_h2h[n * D2 + c] = __float2half_rn(acc);
    float sa = acc * att_s[c];
    float sd = acc * att_d[c];
    #pragma unroll
    for (int off = 8; off > 0; off >>= 1) {
        sa += __shfl_xor_sync(FULL, sa, off);
        sd += __shfl_xor_sync(FULL, sd, off);
    }
    if (c == 0) { g_as2[n] = sa; g_ad2[n] = sd; }
}

// ---------------- layer 2: single-pass softmax-agg ---------------------------
// one warp per dst node; 8 edge subgroups x 4 lanes, each lane owns 4 channels.
// Re-zeros g_cursor after the last read (restores launch invariant).
__global__ void k_l2_agg(const float* __restrict__ bias2,
                         float* __restrict__ out) {
    int n = blockIdx.x * 8 + (threadIdx.x >> 5);
    if (n >= NN) return;
    int lane = threadIdx.x & 31;
    int deg  = min(g_cursor[n], CAP);
    const unsigned short* row = g_bkt + n * CAP;
    float adn = g_ad2[n];

    int q = lane & 3;         // channel quad owner: channels 4q..4q+3
    int g = lane >> 2;        // edge subgroup 0..7

    float a0 = 0.f, a1 = 0.f, a2 = 0.f, a3 = 0.f, wsum = 0.f;
    for (int j = g; j < deg; j += 8) {
        int s = (int)row[j];                           // broadcast in subgroup
        float w = __expf(lrelu(g_as2[s] + adn));       // broadcast load
        uint2 v = *reinterpret_cast<const uint2*>(g_h2h + s * D2 + q * 4);
        float2 f0 = __half22float2(*reinterpret_cast<__half2*>(&v.x));
        float2 f1 = __half22float2(*reinterpret_cast<__half2*>(&v.y));
        a0 = fmaf(w, f0.x, a0);
        a1 = fmaf(w, f0.y, a1);
        a2 = fmaf(w, f1.x, a2);
        a3 = fmaf(w, f1.y, a3);
        wsum += w;
    }
    #pragma unroll
    for (int off = 4; off <= 16; off <<= 1) {
        a0   += __shfl_xor_sync(FULL, a0, off);
        a1   += __shfl_xor_sync(FULL, a1, off);
        a2   += __shfl_xor_sync(FULL, a2, off);
        a3   += __shfl_xor_sync(FULL, a3, off);
        wsum += __shfl_xor_sync(FULL, wsum, off);
    }
    if (lane < 4) {
        float inv = 1.0f / (wsum + 1e-16f);
        int c = q * 4;
        float4 r;
        r.x = a0 * inv + bias2[c];
        r.y = a1 * inv + bias2[c + 1];
        r.z = a2 * inv + bias2[c + 2];
        r.w = a3 * inv + bias2[c + 3];
        *reinterpret_cast<float4*>(out + n * D2 + c) = r;
    }
    if (lane == 0) g_cursor[n] = 0;   // restore zero invariant
}

// ---------------- launch ------------------------------------------------------
extern "C" void kernel_launch(void* const* d_in, const int* in_sizes, int n_in,
                              void* d_out, int out_size) {
    const float* x      = (const float*)d_in[0];
    const int*   ei     = (const int*)d_in[1];   // JAX x64 disabled -> int32
    const float* W1     = (const float*)d_in[2];
    const float* atts1  = (const float*)d_in[3];
    const float* attd1  = (const float*)d_in[4];
    const float* bias1  = (const float*)d_in[5];
    const float* W2     = (const float*)d_in[6];
    const float* atts2  = (const float*)d_in[7];
    const float* attd2  = (const float*)d_in[8];
    const float* bias2  = (const float*)d_in[9];
    float* out = (float*)d_out;

    int sb = (SCAT_T + 255) / 256;
    k_scatter<<<sb + 1, 256>>>(ei, x, W1, atts1, attd1);   // +1 block does prep
    k_l1_agg<<<NN / 16, 512>>>(W1, bias1);
    k_l2_node<<<(NN + 63) / 64, 1024>>>(W2, atts2, attd2);
    k_l2_agg<<<(NN + 7) / 8, 256>>>(bias2, out);
}